// round 14
// baseline (speedup 1.0000x reference)
#include <cuda_runtime.h>
#include <cuda_bf16.h>
#include <cuda_fp16.h>
#include <cstdint>

#define N_    16384
#define DDIM  512
#define BM    128
#define BN    128
#define BK    128              // int8 elems per k-chunk (128 B)
#define NIT   (DDIM / BK)      // 4
#define GT    (N_ / 128)       // 128 tiles per dim

#define RSTRB 144              // padded row stride bytes (128 data + 16 pad)
#define A_BYTES (BM * RSTRB)         // 18432
#define STAGE_BYTES (2 * A_BYTES)    // 36864
#define NSTAGE 3
#define SMEM_TOTAL (NSTAGE * STAGE_BYTES) // 110592

#define LOG2E 1.44269504088896f
#define LN2   0.69314718055995f

// ---------------- device scratch ----------------
__device__ __align__(16) int8_t g_Aq[(size_t)N_ * DDIM];   // 8 MB
__device__ __align__(16) int8_t g_Bq[(size_t)N_ * DDIM];   // 8 MB
__device__ float  g_sA[N_];
__device__ float  g_sB[N_];
__device__ float  g_diag[N_];                    // fp32 dot(A_r, B_r)
__device__ float2 g_rowPart[(size_t)N_ * GT];    // 16 MB (log2-domain)
__device__ float2 g_colPart[(size_t)N_ * GT];    // 16 MB
__device__ float  g_contrib[N_];

// ---------------- helpers ----------------
__device__ __forceinline__ uint32_t smem_u32(const void* p) {
    uint32_t a;
    asm("{ .reg .u64 t; cvta.to.shared.u64 t, %1; cvt.u32.u64 %0, t; }" : "=r"(a) : "l"(p));
    return a;
}
__device__ __forceinline__ void cp16(uint32_t sa, const void* g) {
    asm volatile("cp.async.cg.shared.global [%0], [%1], 16;" :: "r"(sa), "l"(g) : "memory");
}
__device__ __forceinline__ void ldm_x4(uint32_t* d, uint32_t addr) {
    asm volatile("ldmatrix.sync.aligned.m8n8.x4.shared.b16 {%0,%1,%2,%3}, [%4];"
                 : "=r"(d[0]), "=r"(d[1]), "=r"(d[2]), "=r"(d[3]) : "r"(addr));
}
__device__ __forceinline__ void mma_s8(int* d, const uint32_t* a, uint32_t b0, uint32_t b1) {
    asm volatile("mma.sync.aligned.m16n8k32.row.col.s32.s8.s8.s32 "
                 "{%0,%1,%2,%3}, {%4,%5,%6,%7}, {%8,%9}, {%0,%1,%2,%3};"
                 : "+r"(d[0]), "+r"(d[1]), "+r"(d[2]), "+r"(d[3])
                 : "r"(a[0]), "r"(a[1]), "r"(a[2]), "r"(a[3]), "r"(b0), "r"(b1));
}
__device__ __forceinline__ float ex2f(float x) {
    float r; asm("ex2.approx.ftz.f32 %0, %1;" : "=f"(r) : "f"(x)); return r;
}
__device__ __forceinline__ float lg2f(float x) {
    float r; asm("lg2.approx.f32 %0, %1;" : "=f"(r) : "f"(x)); return r;
}
// paired exp2 via f16x2 MUFU (one MUFU op per 2 elements)
__device__ __forceinline__ float2 ex2_pair(float x0, float x1) {
    __half2 h = h2exp2(__floats2half2_rn(x0, x1));
    return __half22float2(h);
}

// ---------------------------------------------------------------------------
// Stage 0: per-row absmax int8 quantization of BOTH matrices + fp32 diag.
// ---------------------------------------------------------------------------
__global__ void __launch_bounds__(128)
clip_quant(const float* __restrict__ A, const float* __restrict__ B)
{
    const int row = blockIdx.x;
    const int t = threadIdx.x;
    __shared__ float sa[4], sbm[4], sd[4];

    float4 va = *(const float4*)(A + (size_t)row * DDIM + t * 4);
    float4 vb = *(const float4*)(B + (size_t)row * DDIM + t * 4);

    float ama = fmaxf(fmaxf(fabsf(va.x), fabsf(va.y)), fmaxf(fabsf(va.z), fabsf(va.w)));
    float amb = fmaxf(fmaxf(fabsf(vb.x), fabsf(vb.y)), fmaxf(fabsf(vb.z), fabsf(vb.w)));
    float d = va.x * vb.x + va.y * vb.y + va.z * vb.z + va.w * vb.w;
    #pragma unroll
    for (int o = 16; o >= 1; o >>= 1) {
        ama = fmaxf(ama, __shfl_xor_sync(0xffffffffu, ama, o));
        amb = fmaxf(amb, __shfl_xor_sync(0xffffffffu, amb, o));
        d += __shfl_xor_sync(0xffffffffu, d, o);
    }
    if ((t & 31) == 0) { sa[t >> 5] = ama; sbm[t >> 5] = amb; sd[t >> 5] = d; }
    __syncthreads();
    ama = fmaxf(fmaxf(sa[0], sa[1]), fmaxf(sa[2], sa[3]));
    amb = fmaxf(fmaxf(sbm[0], sbm[1]), fmaxf(sbm[2], sbm[3]));
    ama = fmaxf(ama, 1e-30f);
    amb = fmaxf(amb, 1e-30f);

    const float ia = 127.0f / ama;
    const float ib = 127.0f / amb;
    char4 qa, qb;
    qa.x = (char)__float2int_rn(va.x * ia); qa.y = (char)__float2int_rn(va.y * ia);
    qa.z = (char)__float2int_rn(va.z * ia); qa.w = (char)__float2int_rn(va.w * ia);
    qb.x = (char)__float2int_rn(vb.x * ib); qb.y = (char)__float2int_rn(vb.y * ib);
    qb.z = (char)__float2int_rn(vb.z * ib); qb.w = (char)__float2int_rn(vb.w * ib);
    *(char4*)(g_Aq + (size_t)row * DDIM + t * 4) = qa;
    *(char4*)(g_Bq + (size_t)row * DDIM + t * 4) = qb;
    if (t == 0) {
        g_sA[row] = ama * (1.0f / 127.0f);
        g_sB[row] = amb * (1.0f / 127.0f);
        g_diag[row] = sd[0] + sd[1] + sd[2] + sd[3];
    }
}

// ---------------------------------------------------------------------------
// Stage 1: int8 mma.sync GEMM (128x128 tile, 2 CTAs/SM) + fused log2-LSE
// ---------------------------------------------------------------------------
__device__ __forceinline__ void load_stage(const int8_t* __restrict__ Ag,
                                           const int8_t* __restrict__ Bg,
                                           int it, int stage, uint32_t sb, int tid)
{
    const uint32_t baseA = sb + stage * STAGE_BYTES;
    const uint32_t baseB = baseA + A_BYTES;
    const int kb = it * BK;
    #pragma unroll
    for (int j = 0; j < 4; j++) {               // A: 128 rows x 8 chunks(16B)
        int idx = tid + j * 256;
        int row = idx >> 3, c = idx & 7;
        cp16(baseA + row * RSTRB + c * 16,
             Ag + (size_t)row * DDIM + kb + c * 16);
    }
    #pragma unroll
    for (int j = 0; j < 4; j++) {               // B: 128 rows x 8 chunks
        int idx = tid + j * 256;
        int row = idx >> 3, c = idx & 7;
        cp16(baseB + row * RSTRB + c * 16,
             Bg + (size_t)row * DDIM + kb + c * 16);
    }
    asm volatile("cp.async.commit_group;" ::: "memory");
}

__global__ void __launch_bounds__(256, 2)
clip_gemm_lse(const float* __restrict__ scale_p)
{
    extern __shared__ char smem[];
    const uint32_t sb = smem_u32(smem);
    const int tid  = threadIdx.x;
    const int wid  = tid >> 5;
    const int lane = tid & 31;
    const int gr   = lane >> 2;     // 0..7
    const int tc   = lane & 3;      // 0..3
    const int wm   = wid >> 2;      // 0..1 : 64-row block
    const int wn   = wid & 3;       // 0..3 : 32-col block

    const int8_t* Ag = g_Aq + (size_t)blockIdx.y * BM * DDIM;
    const int8_t* Bg = g_Bq + (size_t)blockIdx.x * BN * DDIM;

    int acc[4][4][4];
    #pragma unroll
    for (int mi = 0; mi < 4; mi++)
        #pragma unroll
        for (int ni = 0; ni < 4; ni++)
            #pragma unroll
            for (int c = 0; c < 4; c++) acc[mi][ni][c] = 0;

    load_stage(Ag, Bg, 0, 0, sb, tid);
    load_stage(Ag, Bg, 1, 1, sb, tid);

    const int lrow = lane & 15;
    const int lk   = (lane >> 4) * 16;

    for (int it = 0; it < NIT; it++) {
        const int stage = it % NSTAGE;
        if (it < NIT - 2) asm volatile("cp.async.wait_group 1;" ::: "memory");
        else              asm volatile("cp.async.wait_group 0;" ::: "memory");
        __syncthreads();

        if (it + 2 < NIT) load_stage(Ag, Bg, it + 2, (it + 2) % NSTAGE, sb, tid);

        const uint32_t tA = sb + stage * STAGE_BYTES;
        const uint32_t tB = tA + A_BYTES;

        #pragma unroll
        for (int ks = 0; ks < 4; ks++) {        // four k32 steps per 128B chunk
            uint32_t af[4][4], bf[2][4];
            #pragma unroll
            for (int mi = 0; mi < 4; mi++) {
                int r = wm * 64 + mi * 16 + lrow;
                ldm_x4(af[mi], tA + r * RSTRB + ks * 32 + lk);
            }
            #pragma unroll
            for (int nj = 0; nj < 2; nj++) {
                int r = wn * 32 + nj * 16 + lrow;
                ldm_x4(bf[nj], tB + r * RSTRB + ks * 32 + lk);
            }
            #pragma unroll
            for (int mi = 0; mi < 4; mi++)
                #pragma unroll
                for (int ni = 0; ni < 4; ni++) {
                    const int nj = ni >> 1, odd = ni & 1;
                    mma_s8(acc[mi][ni], af[mi], bf[nj][odd], bf[nj][odd + 2]);
                }
        }
        __syncthreads();
    }

    // ---- dequantize in place: logits in log2 units ----
    const float w = __ldg(scale_p) * LOG2E;
    float sRow[8], sCol[8];
    #pragma unroll
    for (int mi = 0; mi < 4; mi++)
        #pragma unroll
        for (int h = 0; h < 2; h++)
            sRow[mi * 2 + h] = g_sA[blockIdx.y * BM + wm * 64 + mi * 16 + h * 8 + gr] * w;
    #pragma unroll
    for (int ni = 0; ni < 4; ni++)
        #pragma unroll
        for (int b = 0; b < 2; b++)
            sCol[ni * 2 + b] = g_sB[blockIdx.x * BN + wn * 32 + ni * 8 + tc * 2 + b];

    float* fa = reinterpret_cast<float*>(&acc[0][0][0]);
    #pragma unroll
    for (int mi = 0; mi < 4; mi++)
        #pragma unroll
        for (int ni = 0; ni < 4; ni++)
            #pragma unroll
            for (int c = 0; c < 4; c++) {
                int iv = acc[mi][ni][c];
                fa[(mi * 4 + ni) * 4 + c] =
                    (float)iv * sRow[mi * 2 + (c >> 1)] * sCol[ni * 2 + (c & 1)];
            }
    #define FACC(mi, ni, c) fa[((mi) * 4 + (ni)) * 4 + (c)]

    // Epilogue smem overlay at stage-1 offset (stages 1,2 dead after mainloop).
    float* ep     = (float*)(smem + STAGE_BYTES);
    float* s_row  = ep;                  // [4][128]
    float* s_col  = s_row + 512;         // [2][128]
    float* s_rowM = s_col + 256;         // [128]
    float* s_colM = s_rowM + 128;        // [128]
    float* s_rsum = s_colM + 128;        // [4][128]
    float* s_csum = s_rsum + 512;        // [2][128]

    // pass 1: maxes
    #pragma unroll
    for (int mi = 0; mi < 4; mi++)
        #pragma unroll
        for (int h = 0; h < 2; h++) {
            float m = -3.0e38f;
            #pragma unroll
            for (int ni = 0; ni < 4; ni++) {
                m = fmaxf(m, FACC(mi, ni, h * 2));
                m = fmaxf(m, FACC(mi, ni, h * 2 + 1));
            }
            m = fmaxf(m, __shfl_xor_sync(0xffffffffu, m, 1));
            m = fmaxf(m, __shfl_xor_sync(0xffffffffu, m, 2));
            if (tc == 0)
                s_row[wn * 128 + wm * 64 + mi * 16 + h * 8 + gr] = m;
        }
    #pragma unroll
    for (int ni = 0; ni < 4; ni++)
        #pragma unroll
        for (int b = 0; b < 2; b++) {
            float m = -3.0e38f;
            #pragma unroll
            for (int mi = 0; mi < 4; mi++) {
                m = fmaxf(m, FACC(mi, ni, b));
                m = fmaxf(m, FACC(mi, ni, 2 + b));
            }
            m = fmaxf(m, __shfl_xor_sync(0xffffffffu, m, 4));
            m = fmaxf(m, __shfl_xor_sync(0xffffffffu, m, 8));
            m = fmaxf(m, __shfl_xor_sync(0xffffffffu, m, 16));
            if (gr == 0)
                s_col[wm * 128 + wn * 32 + ni * 8 + tc * 2 + b] = m;
        }
    __syncthreads();
    if (tid < 128) {
        s_rowM[tid] = fmaxf(fmaxf(s_row[tid], s_row[128 + tid]),
                            fmaxf(s_row[256 + tid], s_row[384 + tid]));
    } else {
        int c = tid - 128;
        s_colM[c] = fmaxf(s_col[c], s_col[128 + c]);
    }
    __syncthreads();

    // pass 2: 2^(v-m) sums via paired f16x2 MUFU (half the EX2 ops)
    float rM[8], cM[8];
    #pragma unroll
    for (int mi = 0; mi < 4; mi++)
        #pragma unroll
        for (int h = 0; h < 2; h++)
            rM[mi * 2 + h] = s_rowM[wm * 64 + mi * 16 + h * 8 + gr];
    #pragma unroll
    for (int ni = 0; ni < 4; ni++)
        #pragma unroll
        for (int b = 0; b < 2; b++)
            cM[ni * 2 + b] = s_colM[wn * 32 + ni * 8 + tc * 2 + b];

    float csum[8];
    #pragma unroll
    for (int k = 0; k < 8; k++) csum[k] = 0.0f;

    #pragma unroll
    for (int mi = 0; mi < 4; mi++)
        #pragma unroll
        for (int h = 0; h < 2; h++) {
            float rs = 0.0f;
            const float rm = rM[mi * 2 + h];
            #pragma unroll
            for (int ni = 0; ni < 4; ni++) {
                const float v0 = FACC(mi, ni, h * 2);
                const float v1 = FACC(mi, ni, h * 2 + 1);
                float2 er = ex2_pair(v0 - rm, v1 - rm);
                rs += er.x + er.y;
                float2 ec = ex2_pair(v0 - cM[ni * 2], v1 - cM[ni * 2 + 1]);
                csum[ni * 2]     += ec.x;
                csum[ni * 2 + 1] += ec.y;
            }
            rs += __shfl_xor_sync(0xffffffffu, rs, 1);
            rs += __shfl_xor_sync(0xffffffffu, rs, 2);
            if (tc == 0)
                s_rsum[wn * 128 + wm * 64 + mi * 16 + h * 8 + gr] = rs;
        }
    #pragma unroll
    for (int ni = 0; ni < 4; ni++)
        #pragma unroll
        for (int b = 0; b < 2; b++) {
            float cs = csum[ni * 2 + b];
            cs += __shfl_xor_sync(0xffffffffu, cs, 4);
            cs += __shfl_xor_sync(0xffffffffu, cs, 8);
            cs += __shfl_xor_sync(0xffffffffu, cs, 16);
            if (gr == 0)
                s_csum[wm * 128 + wn * 32 + ni * 8 + tc * 2 + b] = cs;
        }
    __syncthreads();

    if (tid < 128) {
        float rsum = s_rsum[tid] + s_rsum[128 + tid] + s_rsum[256 + tid] + s_rsum[384 + tid];
        g_rowPart[((size_t)blockIdx.y * BM + tid) * GT + blockIdx.x] =
            make_float2(s_rowM[tid], rsum);
    } else {
        int c = tid - 128;
        float cs = s_csum[c] + s_csum[128 + c];
        g_colPart[((size_t)blockIdx.x * BN + c) * GT + blockIdx.y] =
            make_float2(s_colM[c], cs);
    }
}

// ---------------------------------------------------------------------------
// Stage 2: row and col LSE computed concurrently by thread halves.
// ---------------------------------------------------------------------------
__global__ void __launch_bounds__(256)
clip_finalize(const float* __restrict__ scale_p)
{
    __shared__ float s_m[8], s_s[8], s_lse[2];
    const int r = blockIdx.x;
    const int t = threadIdx.x;
    const int half = t >> 7;          // 0 = row, 1 = col
    const int j = t & 127;
    const int wslot = t >> 5;         // 0..7 (4 warps per half)

    float2 p = half ? g_colPart[(size_t)r * GT + j]
                    : g_rowPart[(size_t)r * GT + j];

    float m = p.x;
    #pragma unroll
    for (int o = 16; o >= 1; o >>= 1)
        m = fmaxf(m, __shfl_xor_sync(0xffffffffu, m, o));
    if ((t & 31) == 0) s_m[wslot] = m;
    __syncthreads();
    const int base = half * 4;
    m = fmaxf(fmaxf(s_m[base], s_m[base + 1]), fmaxf(s_m[base + 2], s_m[base + 3]));

    float e = p.y * ex2f(p.x - m);
    #pragma unroll
    for (int o = 16; o >= 1; o >>= 1)
        e += __shfl_xor_sync(0xffffffffu, e, o);
    if ((t & 31) == 0) s_s[wslot] = e;
    __syncthreads();
    if (j == 0) {
        float s = s_s[base] + s_s[base + 1] + s_s[base + 2] + s_s[base + 3];
        s_lse[half] = LN2 * (m + lg2f(s));
    }
    __syncthreads();
    if (t == 0) {
        const float diag = (*scale_p) * g_diag[r];
        g_contrib[r] = (s_lse[0] - diag) + (s_lse[1] - diag);
    }
}

// ---------------------------------------------------------------------------
// Stage 3: final reduction, 1024 threads with MLP>=4.
// ---------------------------------------------------------------------------
__global__ void __launch_bounds__(1024)
clip_reduce_final(float* __restrict__ out)
{
    __shared__ float red[1024];
    const int t = threadIdx.x;
    const float4* c4 = (const float4*)g_contrib;   // 4096 float4
    float4 v0 = c4[t];
    float4 v1 = c4[t + 1024];
    float4 v2 = c4[t + 2048];
    float4 v3 = c4[t + 3072];
    float s = ((v0.x + v0.y) + (v0.z + v0.w)) + ((v1.x + v1.y) + (v1.z + v1.w))
            + ((v2.x + v2.y) + (v2.z + v2.w)) + ((v3.x + v3.y) + (v3.z + v3.w));
    red[t] = s;  __syncthreads();
    #pragma unroll
    for (int k = 512; k > 0; k >>= 1) { if (t < k) red[t] += red[t + k]; __syncthreads(); }
    if (t == 0) out[0] = red[0] * (0.5f / (float)N_);
}

// ---------------------------------------------------------------------------
extern "C" void kernel_launch(void* const* d_in, const int* in_sizes, int n_in,
                              void* d_out, int out_size)
{
    const float* img   = (const float*)d_in[0];
    const float* txt   = (const float*)d_in[1];
    const float* scale = (const float*)d_in[2];
    float* out = (float*)d_out;

    cudaFuncSetAttribute(clip_gemm_lse, cudaFuncAttributeMaxDynamicSharedMemorySize, SMEM_TOTAL);

    clip_quant<<<N_, 128>>>(img, txt);
    clip_gemm_lse<<<dim3(GT, GT), 256, SMEM_TOTAL>>>(scale);
    clip_finalize<<<N_, 256>>>(scale);
    clip_reduce_final<<<1, 1024>>>(out);
}

// round 15
// speedup vs baseline: 1.0503x; 1.0503x over previous
#include <cuda_runtime.h>
#include <cuda_bf16.h>
#include <cstdint>

#define N_    16384
#define DDIM  512
#define BM    128
#define BN    128
#define BK    128              // int8 elems per k-chunk (128 B)
#define NIT   (DDIM / BK)      // 4
#define GT    (N_ / 128)       // 128 tiles per dim

#define RSTRB 144              // padded row stride bytes (128 data + 16 pad)
#define A_BYTES (BM * RSTRB)         // 18432
#define STAGE_BYTES (2 * A_BYTES)    // 36864
#define NSTAGE 3
#define SMEM_TOTAL (NSTAGE * STAGE_BYTES) // 110592

#define LOG2E 1.44269504088896f
#define LN2   0.69314718055995f

// ---------------- device scratch ----------------
__device__ __align__(16) int8_t g_Aq[(size_t)N_ * DDIM];   // 8 MB
__device__ __align__(16) int8_t g_Bq[(size_t)N_ * DDIM];   // 8 MB
__device__ float  g_sA[N_];
__device__ float  g_sB[N_];
__device__ float  g_diag[N_];                    // fp32 dot(A_r, B_r)
__device__ float2 g_rowPart[(size_t)N_ * GT];    // 16 MB (log2-domain)
__device__ float2 g_colPart[(size_t)N_ * GT];    // 16 MB
__device__ float  g_contrib[N_];
__device__ int    g_ticket;

// ---------------- helpers ----------------
__device__ __forceinline__ uint32_t smem_u32(const void* p) {
    uint32_t a;
    asm("{ .reg .u64 t; cvta.to.shared.u64 t, %1; cvt.u32.u64 %0, t; }" : "=r"(a) : "l"(p));
    return a;
}
__device__ __forceinline__ void cp16(uint32_t sa, const void* g) {
    asm volatile("cp.async.cg.shared.global [%0], [%1], 16;" :: "r"(sa), "l"(g) : "memory");
}
__device__ __forceinline__ void ldm_x4(uint32_t* d, uint32_t addr) {
    asm volatile("ldmatrix.sync.aligned.m8n8.x4.shared.b16 {%0,%1,%2,%3}, [%4];"
                 : "=r"(d[0]), "=r"(d[1]), "=r"(d[2]), "=r"(d[3]) : "r"(addr));
}
__device__ __forceinline__ void mma_s8(int* d, const uint32_t* a, uint32_t b0, uint32_t b1) {
    asm volatile("mma.sync.aligned.m16n8k32.row.col.s32.s8.s8.s32 "
                 "{%0,%1,%2,%3}, {%4,%5,%6,%7}, {%8,%9}, {%0,%1,%2,%3};"
                 : "+r"(d[0]), "+r"(d[1]), "+r"(d[2]), "+r"(d[3])
                 : "r"(a[0]), "r"(a[1]), "r"(a[2]), "r"(a[3]), "r"(b0), "r"(b1));
}
__device__ __forceinline__ float ex2f(float x) {
    float r; asm("ex2.approx.ftz.f32 %0, %1;" : "=f"(r) : "f"(x)); return r;
}
__device__ __forceinline__ float lg2f(float x) {
    float r; asm("lg2.approx.f32 %0, %1;" : "=f"(r) : "f"(x)); return r;
}

// ---------------------------------------------------------------------------
// Stage 0: per-row absmax int8 quantization of BOTH matrices + fp32 diag.
// ---------------------------------------------------------------------------
__global__ void __launch_bounds__(128)
clip_quant(const float* __restrict__ A, const float* __restrict__ B)
{
    const int row = blockIdx.x;
    const int t = threadIdx.x;
    __shared__ float sa[4], sbm[4], sd[4];

    if (row == 0 && t == 0) g_ticket = 0;        // reset finalize ticket each launch

    float4 va = *(const float4*)(A + (size_t)row * DDIM + t * 4);
    float4 vb = *(const float4*)(B + (size_t)row * DDIM + t * 4);

    float ama = fmaxf(fmaxf(fabsf(va.x), fabsf(va.y)), fmaxf(fabsf(va.z), fabsf(va.w)));
    float amb = fmaxf(fmaxf(fabsf(vb.x), fabsf(vb.y)), fmaxf(fabsf(vb.z), fabsf(vb.w)));
    float d = va.x * vb.x + va.y * vb.y + va.z * vb.z + va.w * vb.w;
    #pragma unroll
    for (int o = 16; o >= 1; o >>= 1) {
        ama = fmaxf(ama, __shfl_xor_sync(0xffffffffu, ama, o));
        amb = fmaxf(amb, __shfl_xor_sync(0xffffffffu, amb, o));
        d += __shfl_xor_sync(0xffffffffu, d, o);
    }
    if ((t & 31) == 0) { sa[t >> 5] = ama; sbm[t >> 5] = amb; sd[t >> 5] = d; }
    __syncthreads();
    ama = fmaxf(fmaxf(sa[0], sa[1]), fmaxf(sa[2], sa[3]));
    amb = fmaxf(fmaxf(sbm[0], sbm[1]), fmaxf(sbm[2], sbm[3]));
    ama = fmaxf(ama, 1e-30f);
    amb = fmaxf(amb, 1e-30f);

    const float ia = 127.0f / ama;
    const float ib = 127.0f / amb;
    char4 qa, qb;
    qa.x = (char)__float2int_rn(va.x * ia); qa.y = (char)__float2int_rn(va.y * ia);
    qa.z = (char)__float2int_rn(va.z * ia); qa.w = (char)__float2int_rn(va.w * ia);
    qb.x = (char)__float2int_rn(vb.x * ib); qb.y = (char)__float2int_rn(vb.y * ib);
    qb.z = (char)__float2int_rn(vb.z * ib); qb.w = (char)__float2int_rn(vb.w * ib);
    *(char4*)(g_Aq + (size_t)row * DDIM + t * 4) = qa;
    *(char4*)(g_Bq + (size_t)row * DDIM + t * 4) = qb;
    if (t == 0) {
        g_sA[row] = ama * (1.0f / 127.0f);
        g_sB[row] = amb * (1.0f / 127.0f);
        g_diag[row] = sd[0] + sd[1] + sd[2] + sd[3];
    }
}

// ---------------------------------------------------------------------------
// Stage 1: int8 mma.sync GEMM (128x128 tile, 2 CTAs/SM) + fused log2-LSE
// ---------------------------------------------------------------------------
__device__ __forceinline__ void load_stage(const int8_t* __restrict__ Ag,
                                           const int8_t* __restrict__ Bg,
                                           int it, int stage, uint32_t sb, int tid)
{
    const uint32_t baseA = sb + stage * STAGE_BYTES;
    const uint32_t baseB = baseA + A_BYTES;
    const int kb = it * BK;
    #pragma unroll
    for (int j = 0; j < 4; j++) {               // A: 128 rows x 8 chunks(16B)
        int idx = tid + j * 256;
        int row = idx >> 3, c = idx & 7;
        cp16(baseA + row * RSTRB + c * 16,
             Ag + (size_t)row * DDIM + kb + c * 16);
    }
    #pragma unroll
    for (int j = 0; j < 4; j++) {               // B: 128 rows x 8 chunks
        int idx = tid + j * 256;
        int row = idx >> 3, c = idx & 7;
        cp16(baseB + row * RSTRB + c * 16,
             Bg + (size_t)row * DDIM + kb + c * 16);
    }
    asm volatile("cp.async.commit_group;" ::: "memory");
}

__global__ void __launch_bounds__(256, 2)
clip_gemm_lse(const float* __restrict__ scale_p)
{
    extern __shared__ char smem[];
    const uint32_t sb = smem_u32(smem);
    const int tid  = threadIdx.x;
    const int wid  = tid >> 5;
    const int lane = tid & 31;
    const int gr   = lane >> 2;     // 0..7
    const int tc   = lane & 3;      // 0..3
    const int wm   = wid >> 2;      // 0..1 : 64-row block
    const int wn   = wid & 3;       // 0..3 : 32-col block

    const int8_t* Ag = g_Aq + (size_t)blockIdx.y * BM * DDIM;
    const int8_t* Bg = g_Bq + (size_t)blockIdx.x * BN * DDIM;

    int acc[4][4][4];
    #pragma unroll
    for (int mi = 0; mi < 4; mi++)
        #pragma unroll
        for (int ni = 0; ni < 4; ni++)
            #pragma unroll
            for (int c = 0; c < 4; c++) acc[mi][ni][c] = 0;

    load_stage(Ag, Bg, 0, 0, sb, tid);
    load_stage(Ag, Bg, 1, 1, sb, tid);

    const int lrow = lane & 15;
    const int lk   = (lane >> 4) * 16;

    for (int it = 0; it < NIT; it++) {
        const int stage = it % NSTAGE;
        if (it < NIT - 2) asm volatile("cp.async.wait_group 1;" ::: "memory");
        else              asm volatile("cp.async.wait_group 0;" ::: "memory");
        __syncthreads();

        if (it + 2 < NIT) load_stage(Ag, Bg, it + 2, (it + 2) % NSTAGE, sb, tid);

        const uint32_t tA = sb + stage * STAGE_BYTES;
        const uint32_t tB = tA + A_BYTES;

        #pragma unroll
        for (int ks = 0; ks < 4; ks++) {        // four k32 steps per 128B chunk
            uint32_t af[4][4], bf[2][4];
            #pragma unroll
            for (int mi = 0; mi < 4; mi++) {
                int r = wm * 64 + mi * 16 + lrow;
                ldm_x4(af[mi], tA + r * RSTRB + ks * 32 + lk);
            }
            #pragma unroll
            for (int nj = 0; nj < 2; nj++) {
                int r = wn * 32 + nj * 16 + lrow;
                ldm_x4(bf[nj], tB + r * RSTRB + ks * 32 + lk);
            }
            #pragma unroll
            for (int mi = 0; mi < 4; mi++)
                #pragma unroll
                for (int ni = 0; ni < 4; ni++) {
                    const int nj = ni >> 1, odd = ni & 1;
                    mma_s8(acc[mi][ni], af[mi], bf[nj][odd], bf[nj][odd + 2]);
                }
        }
        __syncthreads();
    }

    // ---- dequantize in place: logits in log2 units ----
    const float w = __ldg(scale_p) * LOG2E;
    float sRow[8], sCol[8];
    #pragma unroll
    for (int mi = 0; mi < 4; mi++)
        #pragma unroll
        for (int h = 0; h < 2; h++)
            sRow[mi * 2 + h] = g_sA[blockIdx.y * BM + wm * 64 + mi * 16 + h * 8 + gr] * w;
    #pragma unroll
    for (int ni = 0; ni < 4; ni++)
        #pragma unroll
        for (int b = 0; b < 2; b++)
            sCol[ni * 2 + b] = g_sB[blockIdx.x * BN + wn * 32 + ni * 8 + tc * 2 + b];

    float* fa = reinterpret_cast<float*>(&acc[0][0][0]);
    #pragma unroll
    for (int mi = 0; mi < 4; mi++)
        #pragma unroll
        for (int ni = 0; ni < 4; ni++)
            #pragma unroll
            for (int c = 0; c < 4; c++) {
                int iv = acc[mi][ni][c];
                fa[(mi * 4 + ni) * 4 + c] =
                    (float)iv * sRow[mi * 2 + (c >> 1)] * sCol[ni * 2 + (c & 1)];
            }
    #define FACC(mi, ni, c) fa[((mi) * 4 + (ni)) * 4 + (c)]

    // Epilogue smem overlay at stage-1 offset (stages 1,2 dead after mainloop).
    float* ep     = (float*)(smem + STAGE_BYTES);
    float* s_row  = ep;                  // [4][128]
    float* s_col  = s_row + 512;         // [2][128]
    float* s_rowM = s_col + 256;         // [128]
    float* s_colM = s_rowM + 128;        // [128]
    float* s_rsum = s_colM + 128;        // [4][128]
    float* s_csum = s_rsum + 512;        // [2][128]

    // pass 1: maxes
    #pragma unroll
    for (int mi = 0; mi < 4; mi++)
        #pragma unroll
        for (int h = 0; h < 2; h++) {
            float m = -3.0e38f;
            #pragma unroll
            for (int ni = 0; ni < 4; ni++) {
                m = fmaxf(m, FACC(mi, ni, h * 2));
                m = fmaxf(m, FACC(mi, ni, h * 2 + 1));
            }
            m = fmaxf(m, __shfl_xor_sync(0xffffffffu, m, 1));
            m = fmaxf(m, __shfl_xor_sync(0xffffffffu, m, 2));
            if (tc == 0)
                s_row[wn * 128 + wm * 64 + mi * 16 + h * 8 + gr] = m;
        }
    #pragma unroll
    for (int ni = 0; ni < 4; ni++)
        #pragma unroll
        for (int b = 0; b < 2; b++) {
            float m = -3.0e38f;
            #pragma unroll
            for (int mi = 0; mi < 4; mi++) {
                m = fmaxf(m, FACC(mi, ni, b));
                m = fmaxf(m, FACC(mi, ni, 2 + b));
            }
            m = fmaxf(m, __shfl_xor_sync(0xffffffffu, m, 4));
            m = fmaxf(m, __shfl_xor_sync(0xffffffffu, m, 8));
            m = fmaxf(m, __shfl_xor_sync(0xffffffffu, m, 16));
            if (gr == 0)
                s_col[wm * 128 + wn * 32 + ni * 8 + tc * 2 + b] = m;
        }
    __syncthreads();
    if (tid < 128) {
        s_rowM[tid] = fmaxf(fmaxf(s_row[tid], s_row[128 + tid]),
                            fmaxf(s_row[256 + tid], s_row[384 + tid]));
    } else {
        int c = tid - 128;
        s_colM[c] = fmaxf(s_col[c], s_col[128 + c]);
    }
    __syncthreads();

    // pass 2: 2^(v-m) sums (f32 MUFU — f16x2 variant measured slower in R14)
    float rM[8], cM[8];
    #pragma unroll
    for (int mi = 0; mi < 4; mi++)
        #pragma unroll
        for (int h = 0; h < 2; h++)
            rM[mi * 2 + h] = s_rowM[wm * 64 + mi * 16 + h * 8 + gr];
    #pragma unroll
    for (int ni = 0; ni < 4; ni++)
        #pragma unroll
        for (int b = 0; b < 2; b++)
            cM[ni * 2 + b] = s_colM[wn * 32 + ni * 8 + tc * 2 + b];

    float csum[8];
    #pragma unroll
    for (int k = 0; k < 8; k++) csum[k] = 0.0f;

    #pragma unroll
    for (int mi = 0; mi < 4; mi++)
        #pragma unroll
        for (int h = 0; h < 2; h++) {
            float rs = 0.0f;
            const float rm = rM[mi * 2 + h];
            #pragma unroll
            for (int ni = 0; ni < 4; ni++)
                #pragma unroll
                for (int b = 0; b < 2; b++) {
                    float v = FACC(mi, ni, h * 2 + b);
                    rs += ex2f(v - rm);
                    csum[ni * 2 + b] += ex2f(v - cM[ni * 2 + b]);
                }
            rs += __shfl_xor_sync(0xffffffffu, rs, 1);
            rs += __shfl_xor_sync(0xffffffffu, rs, 2);
            if (tc == 0)
                s_rsum[wn * 128 + wm * 64 + mi * 16 + h * 8 + gr] = rs;
        }
    #pragma unroll
    for (int ni = 0; ni < 4; ni++)
        #pragma unroll
        for (int b = 0; b < 2; b++) {
            float cs = csum[ni * 2 + b];
            cs += __shfl_xor_sync(0xffffffffu, cs, 4);
            cs += __shfl_xor_sync(0xffffffffu, cs, 8);
            cs += __shfl_xor_sync(0xffffffffu, cs, 16);
            if (gr == 0)
                s_csum[wm * 128 + wn * 32 + ni * 8 + tc * 2 + b] = cs;
        }
    __syncthreads();

    if (tid < 128) {
        float rsum = s_rsum[tid] + s_rsum[128 + tid] + s_rsum[256 + tid] + s_rsum[384 + tid];
        g_rowPart[((size_t)blockIdx.y * BM + tid) * GT + blockIdx.x] =
            make_float2(s_rowM[tid], rsum);
    } else {
        int c = tid - 128;
        float cs = s_csum[c] + s_csum[128 + c];
        g_colPart[((size_t)blockIdx.x * BN + c) * GT + blockIdx.y] =
            make_float2(s_colM[c], cs);
    }
}

// ---------------------------------------------------------------------------
// Stage 2: per-row LSE combine + contrib; last block (ticket) does the final
// deterministic fixed-order reduction and writes the scalar loss.
// ---------------------------------------------------------------------------
__global__ void __launch_bounds__(256)
clip_finalize(const float* __restrict__ scale_p, float* __restrict__ out)
{
    __shared__ float s_m[8], s_s[8], s_lse[2];
    __shared__ float red[256];
    __shared__ bool  s_last;
    const int r = blockIdx.x;
    const int t = threadIdx.x;
    const int half = t >> 7;          // 0 = row, 1 = col
    const int j = t & 127;
    const int wslot = t >> 5;         // 0..7 (4 warps per half)

    float2 p = half ? g_colPart[(size_t)r * GT + j]
                    : g_rowPart[(size_t)r * GT + j];

    float m = p.x;
    #pragma unroll
    for (int o = 16; o >= 1; o >>= 1)
        m = fmaxf(m, __shfl_xor_sync(0xffffffffu, m, o));
    if ((t & 31) == 0) s_m[wslot] = m;
    __syncthreads();
    const int base = half * 4;
    m = fmaxf(fmaxf(s_m[base], s_m[base + 1]), fmaxf(s_m[base + 2], s_m[base + 3]));

    float e = p.y * ex2f(p.x - m);
    #pragma unroll
    for (int o = 16; o >= 1; o >>= 1)
        e += __shfl_xor_sync(0xffffffffu, e, o);
    if ((t & 31) == 0) s_s[wslot] = e;
    __syncthreads();
    if (j == 0) {
        float s = s_s[base] + s_s[base + 1] + s_s[base + 2] + s_s[base + 3];
        s_lse[half] = LN2 * (m + lg2f(s));
    }
    __syncthreads();
    if (t == 0) {
        const float diag = (*scale_p) * g_diag[r];
        g_contrib[r] = (s_lse[0] - diag) + (s_lse[1] - diag);
        __threadfence();
        int old = atomicAdd(&g_ticket, 1);
        s_last = (old == N_ - 1);
    }
    __syncthreads();

    if (s_last) {
        // fixed-order final sum: deterministic regardless of which block runs it
        float s = 0.0f;
        #pragma unroll 4
        for (int i = t; i < N_; i += 256)
            s += __ldcg(&g_contrib[i]);
        red[t] = s;  __syncthreads();
        #pragma unroll
        for (int k = 128; k > 0; k >>= 1) {
            if (t < k) red[t] += red[t + k];
            __syncthreads();
        }
        if (t == 0) out[0] = red[0] * (0.5f / (float)N_);
    }
}

// ---------------------------------------------------------------------------
extern "C" void kernel_launch(void* const* d_in, const int* in_sizes, int n_in,
                              void* d_out, int out_size)
{
    const float* img   = (const float*)d_in[0];
    const float* txt   = (const float*)d_in[1];
    const float* scale = (const float*)d_in[2];
    float* out = (float*)d_out;

    cudaFuncSetAttribute(clip_gemm_lse, cudaFuncAttributeMaxDynamicSharedMemorySize, SMEM_TOTAL);

    clip_quant<<<N_, 128>>>(img, txt);
    clip_gemm_lse<<<dim3(GT, GT), 256, SMEM_TOTAL>>>(scale);
    clip_finalize<<<N_, 256>>>(scale, out);
}

// round 16
// speedup vs baseline: 1.0789x; 1.0272x over previous
#include <cuda_runtime.h>
#include <cuda_bf16.h>
#include <cstdint>

#define N_    16384
#define DDIM  512
#define BM    128
#define BN    128
#define BK    128              // int8 elems per k-chunk (128 B)
#define NIT   (DDIM / BK)      // 4
#define GT    (N_ / 128)       // 128 tiles per dim

#define RSTRB 144              // padded row stride bytes (128 data + 16 pad)
#define A_BYTES (BM * RSTRB)         // 18432
#define STAGE_BYTES (2 * A_BYTES)    // 36864
#define NSTAGE 3
#define SMEM_TOTAL (NSTAGE * STAGE_BYTES) // 110592

#define LOG2E 1.44269504088896f
#define LN2   0.69314718055995f

// ---------------- device scratch ----------------
__device__ __align__(16) int8_t g_Aq[(size_t)N_ * DDIM];   // 8 MB
__device__ __align__(16) int8_t g_Bq[(size_t)N_ * DDIM];   // 8 MB
__device__ float  g_sA[N_];
__device__ float  g_sB[N_];
__device__ float  g_diag[N_];                    // fp32 dot(A_r, B_r)
__device__ float2 g_rowPart[(size_t)N_ * GT];    // 16 MB (log2-domain)
__device__ float2 g_colPart[(size_t)N_ * GT];    // 16 MB
__device__ float  g_contrib[N_];

// ---------------- helpers ----------------
__device__ __forceinline__ uint32_t smem_u32(const void* p) {
    uint32_t a;
    asm("{ .reg .u64 t; cvta.to.shared.u64 t, %1; cvt.u32.u64 %0, t; }" : "=r"(a) : "l"(p));
    return a;
}
__device__ __forceinline__ void cp16(uint32_t sa, const void* g) {
    asm volatile("cp.async.cg.shared.global [%0], [%1], 16;" :: "r"(sa), "l"(g) : "memory");
}
__device__ __forceinline__ void ldm_x4(uint32_t* d, uint32_t addr) {
    asm volatile("ldmatrix.sync.aligned.m8n8.x4.shared.b16 {%0,%1,%2,%3}, [%4];"
                 : "=r"(d[0]), "=r"(d[1]), "=r"(d[2]), "=r"(d[3]) : "r"(addr));
}
__device__ __forceinline__ void mma_s8(int* d, const uint32_t* a, uint32_t b0, uint32_t b1) {
    asm volatile("mma.sync.aligned.m16n8k32.row.col.s32.s8.s8.s32 "
                 "{%0,%1,%2,%3}, {%4,%5,%6,%7}, {%8,%9}, {%0,%1,%2,%3};"
                 : "+r"(d[0]), "+r"(d[1]), "+r"(d[2]), "+r"(d[3])
                 : "r"(a[0]), "r"(a[1]), "r"(a[2]), "r"(a[3]), "r"(b0), "r"(b1));
}
__device__ __forceinline__ float ex2f(float x) {
    float r; asm("ex2.approx.ftz.f32 %0, %1;" : "=f"(r) : "f"(x)); return r;
}
__device__ __forceinline__ float lg2f(float x) {
    float r; asm("lg2.approx.f32 %0, %1;" : "=f"(r) : "f"(x)); return r;
}

// ---------------------------------------------------------------------------
// Stage 0: per-row absmax int8 quantization of BOTH matrices + fp32 diag.
// One WARP per row: no smem, no block sync, MLP=8, coalesced uint4 stores.
// grid = N_/8, block = 256 (8 warps).
// ---------------------------------------------------------------------------
__global__ void __launch_bounds__(256)
clip_quant(const float* __restrict__ A, const float* __restrict__ B)
{
    const int wid  = threadIdx.x >> 5;
    const int lane = threadIdx.x & 31;
    const int row  = blockIdx.x * 8 + wid;
    const size_t base = (size_t)row * DDIM + lane * 16;

    float4 a0 = *(const float4*)(A + base);
    float4 a1 = *(const float4*)(A + base + 4);
    float4 a2 = *(const float4*)(A + base + 8);
    float4 a3 = *(const float4*)(A + base + 12);
    float4 b0 = *(const float4*)(B + base);
    float4 b1 = *(const float4*)(B + base + 4);
    float4 b2 = *(const float4*)(B + base + 8);
    float4 b3 = *(const float4*)(B + base + 12);

    float ama = fmaxf(
        fmaxf(fmaxf(fmaxf(fabsf(a0.x), fabsf(a0.y)), fmaxf(fabsf(a0.z), fabsf(a0.w))),
              fmaxf(fmaxf(fabsf(a1.x), fabsf(a1.y)), fmaxf(fabsf(a1.z), fabsf(a1.w)))),
        fmaxf(fmaxf(fmaxf(fabsf(a2.x), fabsf(a2.y)), fmaxf(fabsf(a2.z), fabsf(a2.w))),
              fmaxf(fmaxf(fabsf(a3.x), fabsf(a3.y)), fmaxf(fabsf(a3.z), fabsf(a3.w)))));
    float amb = fmaxf(
        fmaxf(fmaxf(fmaxf(fabsf(b0.x), fabsf(b0.y)), fmaxf(fabsf(b0.z), fabsf(b0.w))),
              fmaxf(fmaxf(fabsf(b1.x), fabsf(b1.y)), fmaxf(fabsf(b1.z), fabsf(b1.w)))),
        fmaxf(fmaxf(fmaxf(fabsf(b2.x), fabsf(b2.y)), fmaxf(fabsf(b2.z), fabsf(b2.w))),
              fmaxf(fmaxf(fabsf(b3.x), fabsf(b3.y)), fmaxf(fabsf(b3.z), fabsf(b3.w)))));
    float d = a0.x * b0.x + a0.y * b0.y + a0.z * b0.z + a0.w * b0.w
            + a1.x * b1.x + a1.y * b1.y + a1.z * b1.z + a1.w * b1.w
            + a2.x * b2.x + a2.y * b2.y + a2.z * b2.z + a2.w * b2.w
            + a3.x * b3.x + a3.y * b3.y + a3.z * b3.z + a3.w * b3.w;

    #pragma unroll
    for (int o = 16; o >= 1; o >>= 1) {
        ama = fmaxf(ama, __shfl_xor_sync(0xffffffffu, ama, o));
        amb = fmaxf(amb, __shfl_xor_sync(0xffffffffu, amb, o));
        d += __shfl_xor_sync(0xffffffffu, d, o);
    }
    ama = fmaxf(ama, 1e-30f);
    amb = fmaxf(amb, 1e-30f);

    const float ia = 127.0f / ama;
    const float ib = 127.0f / amb;

    // quantize 16 elems of each matrix, pack to uint4, coalesced store
    uint32_t pa[4], pb[4];
    {
        const float4 av[4] = {a0, a1, a2, a3};
        const float4 bv[4] = {b0, b1, b2, b3};
        #pragma unroll
        for (int i = 0; i < 4; i++) {
            char4 qa, qb;
            qa.x = (char)__float2int_rn(av[i].x * ia);
            qa.y = (char)__float2int_rn(av[i].y * ia);
            qa.z = (char)__float2int_rn(av[i].z * ia);
            qa.w = (char)__float2int_rn(av[i].w * ia);
            qb.x = (char)__float2int_rn(bv[i].x * ib);
            qb.y = (char)__float2int_rn(bv[i].y * ib);
            qb.z = (char)__float2int_rn(bv[i].z * ib);
            qb.w = (char)__float2int_rn(bv[i].w * ib);
            pa[i] = *(uint32_t*)&qa;
            pb[i] = *(uint32_t*)&qb;
        }
    }
    *(uint4*)(g_Aq + base) = make_uint4(pa[0], pa[1], pa[2], pa[3]);
    *(uint4*)(g_Bq + base) = make_uint4(pb[0], pb[1], pb[2], pb[3]);
    if (lane == 0) {
        g_sA[row] = ama * (1.0f / 127.0f);
        g_sB[row] = amb * (1.0f / 127.0f);
        g_diag[row] = d;
    }
}

// ---------------------------------------------------------------------------
// Stage 1: int8 mma.sync GEMM (128x128 tile, 2 CTAs/SM) + fused log2-LSE
// ---------------------------------------------------------------------------
__device__ __forceinline__ void load_stage(const int8_t* __restrict__ Ag,
                                           const int8_t* __restrict__ Bg,
                                           int it, int stage, uint32_t sb, int tid)
{
    const uint32_t baseA = sb + stage * STAGE_BYTES;
    const uint32_t baseB = baseA + A_BYTES;
    const int kb = it * BK;
    #pragma unroll
    for (int j = 0; j < 4; j++) {               // A: 128 rows x 8 chunks(16B)
        int idx = tid + j * 256;
        int row = idx >> 3, c = idx & 7;
        cp16(baseA + row * RSTRB + c * 16,
             Ag + (size_t)row * DDIM + kb + c * 16);
    }
    #pragma unroll
    for (int j = 0; j < 4; j++) {               // B: 128 rows x 8 chunks
        int idx = tid + j * 256;
        int row = idx >> 3, c = idx & 7;
        cp16(baseB + row * RSTRB + c * 16,
             Bg + (size_t)row * DDIM + kb + c * 16);
    }
    asm volatile("cp.async.commit_group;" ::: "memory");
}

__global__ void __launch_bounds__(256, 2)
clip_gemm_lse(const float* __restrict__ scale_p)
{
    extern __shared__ char smem[];
    const uint32_t sb = smem_u32(smem);
    const int tid  = threadIdx.x;
    const int wid  = tid >> 5;
    const int lane = tid & 31;
    const int gr   = lane >> 2;     // 0..7
    const int tc   = lane & 3;      // 0..3
    const int wm   = wid >> 2;      // 0..1 : 64-row block
    const int wn   = wid & 3;       // 0..3 : 32-col block

    const int8_t* Ag = g_Aq + (size_t)blockIdx.y * BM * DDIM;
    const int8_t* Bg = g_Bq + (size_t)blockIdx.x * BN * DDIM;

    int acc[4][4][4];
    #pragma unroll
    for (int mi = 0; mi < 4; mi++)
        #pragma unroll
        for (int ni = 0; ni < 4; ni++)
            #pragma unroll
            for (int c = 0; c < 4; c++) acc[mi][ni][c] = 0;

    load_stage(Ag, Bg, 0, 0, sb, tid);
    load_stage(Ag, Bg, 1, 1, sb, tid);

    const int lrow = lane & 15;
    const int lk   = (lane >> 4) * 16;

    for (int it = 0; it < NIT; it++) {
        const int stage = it % NSTAGE;
        if (it < NIT - 2) asm volatile("cp.async.wait_group 1;" ::: "memory");
        else              asm volatile("cp.async.wait_group 0;" ::: "memory");
        __syncthreads();

        if (it + 2 < NIT) load_stage(Ag, Bg, it + 2, (it + 2) % NSTAGE, sb, tid);

        const uint32_t tA = sb + stage * STAGE_BYTES;
        const uint32_t tB = tA + A_BYTES;

        #pragma unroll
        for (int ks = 0; ks < 4; ks++) {        // four k32 steps per 128B chunk
            uint32_t af[4][4], bf[2][4];
            #pragma unroll
            for (int mi = 0; mi < 4; mi++) {
                int r = wm * 64 + mi * 16 + lrow;
                ldm_x4(af[mi], tA + r * RSTRB + ks * 32 + lk);
            }
            #pragma unroll
            for (int nj = 0; nj < 2; nj++) {
                int r = wn * 32 + nj * 16 + lrow;
                ldm_x4(bf[nj], tB + r * RSTRB + ks * 32 + lk);
            }
            #pragma unroll
            for (int mi = 0; mi < 4; mi++)
                #pragma unroll
                for (int ni = 0; ni < 4; ni++) {
                    const int nj = ni >> 1, odd = ni & 1;
                    mma_s8(acc[mi][ni], af[mi], bf[nj][odd], bf[nj][odd + 2]);
                }
        }
        __syncthreads();
    }

    // ---- dequantize in place: logits in log2 units ----
    const float w = __ldg(scale_p) * LOG2E;
    float sRow[8], sCol[8];
    #pragma unroll
    for (int mi = 0; mi < 4; mi++)
        #pragma unroll
        for (int h = 0; h < 2; h++)
            sRow[mi * 2 + h] = g_sA[blockIdx.y * BM + wm * 64 + mi * 16 + h * 8 + gr] * w;
    #pragma unroll
    for (int ni = 0; ni < 4; ni++)
        #pragma unroll
        for (int b = 0; b < 2; b++)
            sCol[ni * 2 + b] = g_sB[blockIdx.x * BN + wn * 32 + ni * 8 + tc * 2 + b];

    float* fa = reinterpret_cast<float*>(&acc[0][0][0]);
    #pragma unroll
    for (int mi = 0; mi < 4; mi++)
        #pragma unroll
        for (int ni = 0; ni < 4; ni++)
            #pragma unroll
            for (int c = 0; c < 4; c++) {
                int iv = acc[mi][ni][c];
                fa[(mi * 4 + ni) * 4 + c] =
                    (float)iv * sRow[mi * 2 + (c >> 1)] * sCol[ni * 2 + (c & 1)];
            }
    #define FACC(mi, ni, c) fa[((mi) * 4 + (ni)) * 4 + (c)]

    // Epilogue smem overlay at stage-1 offset (stages 1,2 dead after mainloop).
    float* ep     = (float*)(smem + STAGE_BYTES);
    float* s_row  = ep;                  // [4][128]
    float* s_col  = s_row + 512;         // [2][128]
    float* s_rowM = s_col + 256;         // [128]
    float* s_colM = s_rowM + 128;        // [128]
    float* s_rsum = s_colM + 128;        // [4][128]
    float* s_csum = s_rsum + 512;        // [2][128]

    // pass 1: maxes
    #pragma unroll
    for (int mi = 0; mi < 4; mi++)
        #pragma unroll
        for (int h = 0; h < 2; h++) {
            float m = -3.0e38f;
            #pragma unroll
            for (int ni = 0; ni < 4; ni++) {
                m = fmaxf(m, FACC(mi, ni, h * 2));
                m = fmaxf(m, FACC(mi, ni, h * 2 + 1));
            }
            m = fmaxf(m, __shfl_xor_sync(0xffffffffu, m, 1));
            m = fmaxf(m, __shfl_xor_sync(0xffffffffu, m, 2));
            if (tc == 0)
                s_row[wn * 128 + wm * 64 + mi * 16 + h * 8 + gr] = m;
        }
    #pragma unroll
    for (int ni = 0; ni < 4; ni++)
        #pragma unroll
        for (int b = 0; b < 2; b++) {
            float m = -3.0e38f;
            #pragma unroll
            for (int mi = 0; mi < 4; mi++) {
                m = fmaxf(m, FACC(mi, ni, b));
                m = fmaxf(m, FACC(mi, ni, 2 + b));
            }
            m = fmaxf(m, __shfl_xor_sync(0xffffffffu, m, 4));
            m = fmaxf(m, __shfl_xor_sync(0xffffffffu, m, 8));
            m = fmaxf(m, __shfl_xor_sync(0xffffffffu, m, 16));
            if (gr == 0)
                s_col[wm * 128 + wn * 32 + ni * 8 + tc * 2 + b] = m;
        }
    __syncthreads();
    if (tid < 128) {
        s_rowM[tid] = fmaxf(fmaxf(s_row[tid], s_row[128 + tid]),
                            fmaxf(s_row[256 + tid], s_row[384 + tid]));
    } else {
        int c = tid - 128;
        s_colM[c] = fmaxf(s_col[c], s_col[128 + c]);
    }
    __syncthreads();

    // pass 2: 2^(v-m) sums
    float rM[8], cM[8];
    #pragma unroll
    for (int mi = 0; mi < 4; mi++)
        #pragma unroll
        for (int h = 0; h < 2; h++)
            rM[mi * 2 + h] = s_rowM[wm * 64 + mi * 16 + h * 8 + gr];
    #pragma unroll
    for (int ni = 0; ni < 4; ni++)
        #pragma unroll
        for (int b = 0; b < 2; b++)
            cM[ni * 2 + b] = s_colM[wn * 32 + ni * 8 + tc * 2 + b];

    float csum[8];
    #pragma unroll
    for (int k = 0; k < 8; k++) csum[k] = 0.0f;

    #pragma unroll
    for (int mi = 0; mi < 4; mi++)
        #pragma unroll
        for (int h = 0; h < 2; h++) {
            float rs = 0.0f;
            const float rm = rM[mi * 2 + h];
            #pragma unroll
            for (int ni = 0; ni < 4; ni++)
                #pragma unroll
                for (int b = 0; b < 2; b++) {
                    float v = FACC(mi, ni, h * 2 + b);
                    rs += ex2f(v - rm);
                    csum[ni * 2 + b] += ex2f(v - cM[ni * 2 + b]);
                }
            rs += __shfl_xor_sync(0xffffffffu, rs, 1);
            rs += __shfl_xor_sync(0xffffffffu, rs, 2);
            if (tc == 0)
                s_rsum[wn * 128 + wm * 64 + mi * 16 + h * 8 + gr] = rs;
        }
    #pragma unroll
    for (int ni = 0; ni < 4; ni++)
        #pragma unroll
        for (int b = 0; b < 2; b++) {
            float cs = csum[ni * 2 + b];
            cs += __shfl_xor_sync(0xffffffffu, cs, 4);
            cs += __shfl_xor_sync(0xffffffffu, cs, 8);
            cs += __shfl_xor_sync(0xffffffffu, cs, 16);
            if (gr == 0)
                s_csum[wm * 128 + wn * 32 + ni * 8 + tc * 2 + b] = cs;
        }
    __syncthreads();

    if (tid < 128) {
        float rsum = s_rsum[tid] + s_rsum[128 + tid] + s_rsum[256 + tid] + s_rsum[384 + tid];
        g_rowPart[((size_t)blockIdx.y * BM + tid) * GT + blockIdx.x] =
            make_float2(s_rowM[tid], rsum);
    } else {
        int c = tid - 128;
        float cs = s_csum[c] + s_csum[128 + c];
        g_colPart[((size_t)blockIdx.x * BN + c) * GT + blockIdx.y] =
            make_float2(s_colM[c], cs);
    }
}

// ---------------------------------------------------------------------------
// Stage 2: row and col LSE computed concurrently by thread halves.
// ---------------------------------------------------------------------------
__global__ void __launch_bounds__(256)
clip_finalize(const float* __restrict__ scale_p)
{
    __shared__ float s_m[8], s_s[8], s_lse[2];
    const int r = blockIdx.x;
    const int t = threadIdx.x;
    const int half = t >> 7;          // 0 = row, 1 = col
    const int j = t & 127;
    const int wslot = t >> 5;         // 0..7 (4 warps per half)

    float2 p = half ? g_colPart[(size_t)r * GT + j]
                    : g_rowPart[(size_t)r * GT + j];

    float m = p.x;
    #pragma unroll
    for (int o = 16; o >= 1; o >>= 1)
        m = fmaxf(m, __shfl_xor_sync(0xffffffffu, m, o));
    if ((t & 31) == 0) s_m[wslot] = m;
    __syncthreads();
    const int base = half * 4;
    m = fmaxf(fmaxf(s_m[base], s_m[base + 1]), fmaxf(s_m[base + 2], s_m[base + 3]));

    float e = p.y * ex2f(p.x - m);
    #pragma unroll
    for (int o = 16; o >= 1; o >>= 1)
        e += __shfl_xor_sync(0xffffffffu, e, o);
    if ((t & 31) == 0) s_s[wslot] = e;
    __syncthreads();
    if (j == 0) {
        float s = s_s[base] + s_s[base + 1] + s_s[base + 2] + s_s[base + 3];
        s_lse[half] = LN2 * (m + lg2f(s));
    }
    __syncthreads();
    if (t == 0) {
        const float diag = (*scale_p) * g_diag[r];
        g_contrib[r] = (s_lse[0] - diag) + (s_lse[1] - diag);
    }
}

// ---------------------------------------------------------------------------
// Stage 3: final reduction, 1024 threads with MLP>=4.
// ---------------------------------------------------------------------------
__global__ void __launch_bounds__(1024)
clip_reduce_final(float* __restrict__ out)
{
    __shared__ float red[1024];
    const int t = threadIdx.x;
    const float4* c4 = (const float4*)g_contrib;   // 4096 float4
    float4 v0 = c4[t];
    float4 v1 = c4[t + 1024];
    float4 v2 = c4[t + 2048];
    float4 v3 = c4[t + 3072];
    float s = ((v0.x + v0.y) + (v0.z + v0.w)) + ((v1.x + v1.y) + (v1.z + v1.w))
            + ((v2.x + v2.y) + (v2.z + v2.w)) + ((v3.x + v3.y) + (v3.z + v3.w));
    red[t] = s;  __syncthreads();
    #pragma unroll
    for (int k = 512; k > 0; k >>= 1) { if (t < k) red[t] += red[t + k]; __syncthreads(); }
    if (t == 0) out[0] = red[0] * (0.5f / (float)N_);
}

// ---------------------------------------------------------------------------
extern "C" void kernel_launch(void* const* d_in, const int* in_sizes, int n_in,
                              void* d_out, int out_size)
{
    const float* img   = (const float*)d_in[0];
    const float* txt   = (const float*)d_in[1];
    const float* scale = (const float*)d_in[2];
    float* out = (float*)d_out;

    cudaFuncSetAttribute(clip_gemm_lse, cudaFuncAttributeMaxDynamicSharedMemorySize, SMEM_TOTAL);

    clip_quant<<<N_ / 8, 256>>>(img, txt);
    clip_gemm_lse<<<dim3(GT, GT), 256, SMEM_TOTAL>>>(scale);
    clip_finalize<<<N_, 256>>>(scale);
    clip_reduce_final<<<1, 1024>>>(out);
}